// round 5
// baseline (speedup 1.0000x reference)
#include <cuda_runtime.h>

// ---------------------------------------------------------------------------
// LinkWeightDecoder: out[e] = MLP(concat(emb[src_e], emb[dst_e]))
//   K1: P[n][0:128]  = emb[n] @ W1[:128]  + b1   (src proj, bias folded)
//       P[n][128:256]= emb[n] @ W1[128:]         (dst proj)
//   K2 (persistent, 128-edge tiles, k-split):
//       h1 = relu(P[src][0:128] + P[dst][128:256])
//       h2 = relu(h1 @ W2 + b2) ; out = h2 @ W3 + b3
// Microtile 8 edges x 8 outs per thread (2B LDS per fma2), fma.rn.f32x2.
// ---------------------------------------------------------------------------

#define MAXN 100000
#define NSM  148

// edge_kernel dynamic smem (floats):
//   sH1 : 128*128 = 16384   (64 KB)   also reused as partial-sum buffer
//   sW2 : 128*72  = 9216    (36 KB)   split-row layout (bank-conflict-free)
//   sW3 : 64
//   sIdx: 256 ints
#define SH1_FLOATS 16384
#define SW2_FLOATS (128 * 72)
#define EDGE_SMEM_BYTES ((SH1_FLOATS + SW2_FLOATS + 64) * 4 + 256 * 4)

__device__ float g_P[MAXN * 256];   // per-node projections (102.4 MB)

__device__ __forceinline__ unsigned long long pack2(float lo, float hi) {
    unsigned long long r;
    asm("mov.b64 %0, {%1, %2};" : "=l"(r) : "f"(lo), "f"(hi));
    return r;
}
__device__ __forceinline__ void unpack2(unsigned long long v, float& lo, float& hi) {
    asm("mov.b64 {%0, %1}, %2;" : "=f"(lo), "=f"(hi) : "l"(v));
}
__device__ __forceinline__ void fma2(unsigned long long& d,
                                     unsigned long long a, unsigned long long b) {
    asm("fma.rn.f32x2 %0, %1, %2, %0;" : "+l"(d) : "l"(a), "l"(b));
}
__device__ __forceinline__ void add2(unsigned long long& d, unsigned long long a) {
    asm("add.rn.f32x2 %0, %0, %1;" : "+l"(d) : "l"(a));
}

// ---------------------------------------------------------------------------
// Kernel 1: P = emb @ [W1a | W1b]   ([N,128] x [128,256])  (unchanged)
// ---------------------------------------------------------------------------
__global__ __launch_bounds__(256, 2)
void precompute_kernel(const float* __restrict__ emb,
                       const float* __restrict__ W1,
                       const float* __restrict__ b1, int N) {
    __shared__ float sW1c[32 * 260];
    __shared__ float sEmb[64 * 33];

    const int tid  = threadIdx.x;
    const int lane = tid & 31, w = tid >> 5;
    const int wx = w & 3, wy = w >> 2;
    const int lx = lane & 7, ly = lane >> 3;
    const int o0  = wx * 64 + lx * 8;
    const int nl0 = wy * 32 + ly * 8;
    const int gn0 = blockIdx.x * 64;

    unsigned long long acc[8][4];
#pragma unroll
    for (int i = 0; i < 8; i++)
#pragma unroll
        for (int p = 0; p < 4; p++) acc[i][p] = 0ull;

    for (int kc = 0; kc < 4; kc++) {
#pragma unroll
        for (int it = 0; it < 2; it++) {
            int slot = it * 256 + tid;
            int node = slot >> 3, kg = slot & 7;
            int gnode = gn0 + node; if (gnode >= N) gnode = N - 1;
            float4 v = *(const float4*)&emb[(long long)gnode * 128 + kc * 32 + kg * 4];
            float* dp = &sEmb[node * 33 + kg * 4];
            dp[0] = v.x; dp[1] = v.y; dp[2] = v.z; dp[3] = v.w;
        }
#pragma unroll
        for (int it = 0; it < 8; it++) {
            int slot = it * 256 + tid;
            int dk = slot >> 6, og = slot & 63;
            int o = og * 4;
            int gk = kc * 32 + dk;
            const float* sp = (o < 128) ? &W1[gk * 128 + o]
                                        : &W1[(gk + 128) * 128 + (o - 128)];
            *(float4*)&sW1c[dk * 260 + o] = *(const float4*)sp;
        }
        __syncthreads();

#pragma unroll
        for (int dk = 0; dk < 32; dk++) {
            const ulonglong2* wp = (const ulonglong2*)&sW1c[dk * 260 + o0];
            ulonglong2 wa = wp[0], wb = wp[1];
#pragma unroll
            for (int i = 0; i < 8; i++) {
                float ev = sEmb[(nl0 + i) * 33 + dk];
                unsigned long long ee = pack2(ev, ev);
                fma2(acc[i][0], ee, wa.x);
                fma2(acc[i][1], ee, wa.y);
                fma2(acc[i][2], ee, wb.x);
                fma2(acc[i][3], ee, wb.y);
            }
        }
        __syncthreads();
    }

    float bb[8];
#pragma unroll
    for (int j = 0; j < 8; j++) bb[j] = (o0 < 128) ? __ldg(&b1[o0 + j]) : 0.f;

#pragma unroll
    for (int i = 0; i < 8; i++) {
        int gnode = gn0 + nl0 + i;
        if (gnode < N) {
            float v[8];
#pragma unroll
            for (int p = 0; p < 4; p++) unpack2(acc[i][p], v[2 * p], v[2 * p + 1]);
#pragma unroll
            for (int j = 0; j < 8; j++) v[j] += bb[j];
            float4* op = (float4*)&g_P[(long long)gnode * 256 + o0];
            op[0] = make_float4(v[0], v[1], v[2], v[3]);
            op[1] = make_float4(v[4], v[5], v[6], v[7]);
        }
    }
}

// ---------------------------------------------------------------------------
// Kernel 2 (persistent): 128-edge tiles, microtile 8e x 8o, k-split halves.
// Thread map: kh=tid>>7 (k-half); lane og=lane&7 -> outs og*8..+7;
//             eg=((tid>>5)&3)*4 + (lane>>3) -> edges eg*8..+7.
// sW2 split-row layout: col(o) = o + 4*(o>=32), stride 72 -> conflict-free.
// ---------------------------------------------------------------------------
__global__ __launch_bounds__(256, 2)
void edge_kernel(const int* __restrict__ eidx_w,
                 const float* __restrict__ W2,
                 const float* __restrict__ b2,
                 const float* __restrict__ W3,
                 const float* __restrict__ b3,
                 float* __restrict__ out, int E, int N, int nTiles) {
    extern __shared__ float dsm[];
    float* sH1 = dsm;                        // [edge][k], stride 128
    float* sW2 = dsm + SH1_FLOATS;           // [k][72] split layout
    float* sW3 = sW2 + SW2_FLOATS;           // [64]
    int*   sIdx = (int*)(sW3 + 64);          // [0:128)=src, [128:256)=dst
    unsigned long long* sP = (unsigned long long*)sH1;  // partial buffer (reuse)
    __shared__ int sAny;

    const int tid  = threadIdx.x;
    const int lane = tid & 31;

    // ---- one-time staging: W2 (split layout), W3, index-dtype detection ----
    if (tid == 0) sAny = 0;
    __syncthreads();
    if (tid < 64) {
        if (eidx_w[2 * tid + 1] != 0) atomicOr(&sAny, 1);  // int32 if any nonzero
    }
#pragma unroll
    for (int it = 0; it < 32; it++) {
        int slot = it * 256 + tid;
        int dk = slot >> 6, o = slot & 63;
        sW2[dk * 72 + o + ((o >= 32) ? 4 : 0)] = W2[dk * 64 + o];
    }
    if (tid < 64) sW3[tid] = W3[tid];
    __syncthreads();
    const int stride = sAny ? 1 : 2;   // words per index element

    // GEMM mapping
    const int kh  = tid >> 7;                 // k-half 0/1
    const int og  = lane & 7;                 // out group: outs og*8..+7
    const int ly  = lane >> 3;
    const int eg  = ((tid >> 5) & 3) * 4 + ly;   // edge group 0..15
    const int k0  = kh * 64;
    const int wcol = og * 8 + ((og >> 2) << 2);  // split-layout column
    const int u   = tid & 127;                   // id within k-half

    // epilogue constants (8 outs of this thread)
    const float4 b2a = __ldg((const float4*)&b2[og * 8]);
    const float4 b2b = __ldg((const float4*)&b2[og * 8 + 4]);
    const float4 w3a = *(const float4*)&sW3[og * 8];
    const float4 w3b = *(const float4*)&sW3[og * 8 + 4];
    const float  bias3 = __ldg(&b3[0]);

    const float4* P4 = (const float4*)g_P;
    const int grid = gridDim.x;
    const int w = tid >> 5;

    for (int t = blockIdx.x; t < nTiles; t += grid) {
        // ---- (a) load indices ----
        {
            int r = tid & 127;
            int e = t * 128 + r; if (e >= E) e = E - 1;
            long long off = (tid < 128) ? (long long)e * stride
                                        : ((long long)E + e) * stride;
            int v = eidx_w[off];
            sIdx[tid] = min(max(v, 0), N - 1);
        }
        __syncthreads();   // (b) prev epilogue reads done + sIdx ready

        // ---- (c) gather + combine -> sH1 ----
#pragma unroll
        for (int i = 0; i < 16; i++) {
            int e = i * 8 + w;            // 0..127, per-warp edge
            int si = sIdx[e], di = sIdx[128 + e];
            float4 a = __ldg(&P4[(long long)si * 64 + lane]);
            float4 b = __ldg(&P4[(long long)di * 64 + 32 + lane]);
            float4 h;
            h.x = fmaxf(a.x + b.x, 0.f);
            h.y = fmaxf(a.y + b.y, 0.f);
            h.z = fmaxf(a.z + b.z, 0.f);
            h.w = fmaxf(a.w + b.w, 0.f);
            *(float4*)&sH1[e * 128 + lane * 4] = h;
        }
        __syncthreads();   // (d)

        // ---- (e) GEMM: [128e x 64k-half] @ [64k x 64o] partial ----
        unsigned long long acc[8][4];
#pragma unroll
        for (int i = 0; i < 8; i++)
#pragma unroll
            for (int p = 0; p < 4; p++) acc[i][p] = 0ull;

#pragma unroll
        for (int dk = 0; dk < 64; dk += 4) {
            int k = k0 + dk;
            ulonglong2 wvA[4], wvB[4];
#pragma unroll
            for (int kk = 0; kk < 4; kk++) {
                wvA[kk] = *(const ulonglong2*)&sW2[(k + kk) * 72 + wcol];
                wvB[kk] = *(const ulonglong2*)&sW2[(k + kk) * 72 + wcol + 4];
            }
#pragma unroll
            for (int i = 0; i < 8; i++) {
                float4 hv = *(const float4*)&sH1[(eg * 8 + i) * 128 + k];
#pragma unroll
                for (int kk = 0; kk < 4; kk++) {
                    float hx = (kk == 0) ? hv.x : (kk == 1) ? hv.y
                             : (kk == 2) ? hv.z : hv.w;
                    unsigned long long hh = pack2(hx, hx);
                    fma2(acc[i][0], hh, wvA[kk].x);
                    fma2(acc[i][1], hh, wvA[kk].y);
                    fma2(acc[i][2], hh, wvB[kk].x);
                    fma2(acc[i][3], hh, wvB[kk].y);
                }
            }
        }
        __syncthreads();   // (f) GEMM reads of sH1 done

        // ---- (g) k-half 1 publishes partials into sP (=sH1 region) ----
        if (kh == 1) {
#pragma unroll
            for (int i = 0; i < 8; i++)
#pragma unroll
                for (int p = 0; p < 4; p++)
                    sP[(i * 4 + p) * 128 + u] = acc[i][p];
        }
        __syncthreads();   // (h)

        // ---- (i) k-half 0 combines + epilogue ----
        if (kh == 0) {
#pragma unroll
            for (int i = 0; i < 8; i++) {
#pragma unroll
                for (int p = 0; p < 4; p++)
                    add2(acc[i][p], sP[(i * 4 + p) * 128 + u]);

                float v0, v1, v2, v3, v4, v5, v6, v7;
                unpack2(acc[i][0], v0, v1);
                unpack2(acc[i][1], v2, v3);
                unpack2(acc[i][2], v4, v5);
                unpack2(acc[i][3], v6, v7);
                float s = fmaxf(v0 + b2a.x, 0.f) * w3a.x
                        + fmaxf(v1 + b2a.y, 0.f) * w3a.y
                        + fmaxf(v2 + b2a.z, 0.f) * w3a.z
                        + fmaxf(v3 + b2a.w, 0.f) * w3a.w
                        + fmaxf(v4 + b2b.x, 0.f) * w3b.x
                        + fmaxf(v5 + b2b.y, 0.f) * w3b.y
                        + fmaxf(v6 + b2b.z, 0.f) * w3b.z
                        + fmaxf(v7 + b2b.w, 0.f) * w3b.w;
                // reduce across og lanes (bits 0..2 of lane)
                s += __shfl_xor_sync(0xffffffffu, s, 4);
                s += __shfl_xor_sync(0xffffffffu, s, 2);
                s += __shfl_xor_sync(0xffffffffu, s, 1);
                if (og == 0) {
                    int e = t * 128 + eg * 8 + i;
                    if (e < E) out[e] = s + bias3;
                }
            }
        }
        // next iteration's (b) sync guards sP reads vs sH1 overwrite
    }
}

// ---------------------------------------------------------------------------
extern "C" void kernel_launch(void* const* d_in, const int* in_sizes, int n_in,
                              void* d_out, int out_size) {
    const float* emb    = (const float*)d_in[0];
    const int*   eidx_w = (const int*)d_in[1];
    const float* W1     = (const float*)d_in[2];
    const float* b1     = (const float*)d_in[3];
    const float* W2     = (const float*)d_in[4];
    const float* b2     = (const float*)d_in[5];
    const float* W3     = (const float*)d_in[6];
    const float* b3     = (const float*)d_in[7];

    int N = in_sizes[0] / 128;
    int E = in_sizes[1] / 2;
    int nTiles = (E + 127) / 128;

    static int smem_set = 0;
    if (!smem_set) {
        cudaFuncSetAttribute(edge_kernel,
                             cudaFuncAttributeMaxDynamicSharedMemorySize,
                             EDGE_SMEM_BYTES);
        smem_set = 1;
    }

    precompute_kernel<<<(N + 63) / 64, 256>>>(emb, W1, b1, N);
    edge_kernel<<<2 * NSM, 256, EDGE_SMEM_BYTES>>>(eidx_w, W2, b2, W3, b3,
                                                   (float*)d_out, E, N, nTiles);
}

// round 6
// speedup vs baseline: 1.1069x; 1.1069x over previous
#include <cuda_runtime.h>

// ---------------------------------------------------------------------------
// LinkWeightDecoder: out[e] = MLP(concat(emb[src_e], emb[dst_e]))
//   K1: P[n][0:128]  = emb[n] @ W1[:128]  + b1   (src proj, bias folded)
//       P[n][128:256]= emb[n] @ W1[128:]         (dst proj)
//   K2 (persistent, 128-edge tiles):
//       h1 = relu(P[src][0:128] + P[dst][128:256])
//       h2 = relu(h1 @ W2 + b2) ; out = h2 @ W3 + b3
// Microtile 4 edges x 8 outs (32 acc regs, 3B LDS per fma2), fma.rn.f32x2.
// ---------------------------------------------------------------------------

#define MAXN 100000
#define NSM  148

// edge_kernel dynamic smem (floats):
//   sH1 : 128*132 = 16896  (67.6 KB)  stride 132 -> conflict-free GEMM reads
//   sW2 : 128*72  = 9216   (36.9 KB)  split-row layout (conflict-free)
//   sW3 : 64
#define SH1_STRIDE 132
#define SH1_FLOATS (128 * SH1_STRIDE)
#define SW2_FLOATS (128 * 72)
#define EDGE_SMEM_BYTES ((SH1_FLOATS + SW2_FLOATS + 64) * 4)

__device__ float g_P[MAXN * 256];   // per-node projections (102.4 MB)

__device__ __forceinline__ unsigned long long pack2(float lo, float hi) {
    unsigned long long r;
    asm("mov.b64 %0, {%1, %2};" : "=l"(r) : "f"(lo), "f"(hi));
    return r;
}
__device__ __forceinline__ void unpack2(unsigned long long v, float& lo, float& hi) {
    asm("mov.b64 {%0, %1}, %2;" : "=f"(lo), "=f"(hi) : "l"(v));
}
__device__ __forceinline__ void fma2(unsigned long long& d,
                                     unsigned long long a, unsigned long long b) {
    asm("fma.rn.f32x2 %0, %1, %2, %0;" : "+l"(d) : "l"(a), "l"(b));
}

// ---------------------------------------------------------------------------
// Kernel 1: P = emb @ [W1a | W1b]   ([N,128] x [128,256])
// sW1c uses split-row layout (4-float pad per 32) -> conflict-free LDS.128.
// ---------------------------------------------------------------------------
__global__ __launch_bounds__(256, 2)
void precompute_kernel(const float* __restrict__ emb,
                       const float* __restrict__ W1,
                       const float* __restrict__ b1, int N) {
    __shared__ float sW1c[32 * 288];   // [dk][o'] split layout
    __shared__ float sEmb[64 * 33];

    const int tid  = threadIdx.x;
    const int lane = tid & 31, w = tid >> 5;
    const int wx = w & 3, wy = w >> 2;
    const int lx = lane & 7, ly = lane >> 3;
    const int o0  = wx * 64 + lx * 8;
    const int oc0 = o0 + ((o0 >> 5) << 2);   // split-layout column of o0
    const int nl0 = wy * 32 + ly * 8;
    const int gn0 = blockIdx.x * 64;

    unsigned long long acc[8][4];
#pragma unroll
    for (int i = 0; i < 8; i++)
#pragma unroll
        for (int p = 0; p < 4; p++) acc[i][p] = 0ull;

    for (int kc = 0; kc < 4; kc++) {
#pragma unroll
        for (int it = 0; it < 2; it++) {
            int slot = it * 256 + tid;
            int node = slot >> 3, kg = slot & 7;
            int gnode = gn0 + node; if (gnode >= N) gnode = N - 1;
            float4 v = *(const float4*)&emb[(long long)gnode * 128 + kc * 32 + kg * 4];
            float* dp = &sEmb[node * 33 + kg * 4];
            dp[0] = v.x; dp[1] = v.y; dp[2] = v.z; dp[3] = v.w;
        }
#pragma unroll
        for (int it = 0; it < 8; it++) {
            int slot = it * 256 + tid;
            int dk = slot >> 6, og = slot & 63;
            int o = og * 4;
            int oc = o + ((o >> 5) << 2);
            int gk = kc * 32 + dk;
            const float* sp = (o < 128) ? &W1[gk * 128 + o]
                                        : &W1[(gk + 128) * 128 + (o - 128)];
            *(float4*)&sW1c[dk * 288 + oc] = *(const float4*)sp;
        }
        __syncthreads();

#pragma unroll
        for (int dk = 0; dk < 32; dk++) {
            const ulonglong2* wp = (const ulonglong2*)&sW1c[dk * 288 + oc0];
            ulonglong2 wa = wp[0], wb = wp[1];
#pragma unroll
            for (int i = 0; i < 8; i++) {
                float ev = sEmb[(nl0 + i) * 33 + dk];
                unsigned long long ee = pack2(ev, ev);
                fma2(acc[i][0], ee, wa.x);
                fma2(acc[i][1], ee, wa.y);
                fma2(acc[i][2], ee, wb.x);
                fma2(acc[i][3], ee, wb.y);
            }
        }
        __syncthreads();
    }

    float bb[8];
#pragma unroll
    for (int j = 0; j < 8; j++) bb[j] = (o0 < 128) ? __ldg(&b1[o0 + j]) : 0.f;

#pragma unroll
    for (int i = 0; i < 8; i++) {
        int gnode = gn0 + nl0 + i;
        if (gnode < N) {
            float v[8];
#pragma unroll
            for (int p = 0; p < 4; p++) unpack2(acc[i][p], v[2 * p], v[2 * p + 1]);
#pragma unroll
            for (int j = 0; j < 8; j++) v[j] += bb[j];
            float4* op = (float4*)&g_P[(long long)gnode * 256 + o0];
            op[0] = make_float4(v[0], v[1], v[2], v[3]);
            op[1] = make_float4(v[4], v[5], v[6], v[7]);
        }
    }
}

// ---------------------------------------------------------------------------
// Kernel 2 (persistent): 128-edge tiles, microtile 4e x 8o, full k=128.
// Thread map: og = tid&7 (outs og*8..+7), eg = tid>>3 (edges eg*4..+3).
// Gather: warp w owns edges w*16..w*16+15; idx via 1 LDG/lane + shfl.
// ---------------------------------------------------------------------------
__global__ __launch_bounds__(256, 2)
void edge_kernel(const int* __restrict__ eidx_w,
                 const float* __restrict__ W2,
                 const float* __restrict__ b2,
                 const float* __restrict__ W3,
                 const float* __restrict__ b3,
                 float* __restrict__ out, int E, int N, int nTiles) {
    extern __shared__ float dsm[];
    float* sH1 = dsm;                        // [128][132]
    float* sW2 = dsm + SH1_FLOATS;           // [128][72] split layout
    float* sW3 = sW2 + SW2_FLOATS;           // [64]
    __shared__ int sAny;

    const int tid  = threadIdx.x;
    const int lane = tid & 31, w = tid >> 5;

    // ---- one-time staging: W2 (split layout), W3, index-dtype detection ----
    if (tid == 0) sAny = 0;
    __syncthreads();
    if (tid < 64) {
        if (eidx_w[2 * tid + 1] != 0) atomicOr(&sAny, 1);  // nonzero -> int32
    }
#pragma unroll
    for (int it = 0; it < 32; it++) {
        int slot = it * 256 + tid;
        int dk = slot >> 6, o = slot & 63;
        sW2[dk * 72 + o + ((o >= 32) ? 4 : 0)] = W2[dk * 64 + o];
    }
    if (tid < 64) sW3[tid] = W3[tid];
    __syncthreads();
    const int stride = sAny ? 1 : 2;   // words per index element

    // GEMM mapping
    const int og = tid & 7;                  // out group: outs og*8..+7
    const int eg = tid >> 3;                 // edge group: edges eg*4..+3
    const int wcol = og * 8 + ((og >> 2) << 2);  // split-layout column

    // epilogue constants
    const float4 b2a = __ldg((const float4*)&b2[og * 8]);
    const float4 b2b = __ldg((const float4*)&b2[og * 8 + 4]);
    const float4 w3a = *(const float4*)&sW3[og * 8];
    const float4 w3b = *(const float4*)&sW3[og * 8 + 4];
    const float  bias3 = __ldg(&b3[0]);

    const float4* P4 = (const float4*)g_P;
    const int grid = gridDim.x;

    for (int t = blockIdx.x; t < nTiles; t += grid) {
        // ---- idx: warp w owns edges t*128 + w*16 .. +15 ----
        int myidx;
        {
            int l = lane & 15;
            int e = t * 128 + w * 16 + l; if (e >= E) e = E - 1;
            long long off = (lane < 16) ? (long long)e * stride
                                        : ((long long)E + e) * stride;
            int v = eidx_w[off];
            myidx = min(max(v, 0), N - 1);
        }

        // ---- gather + combine -> sH1 (warp-local rows, no pre-barrier) ----
#pragma unroll 8
        for (int i = 0; i < 16; i++) {
            int si = __shfl_sync(0xffffffffu, myidx, i);
            int di = __shfl_sync(0xffffffffu, myidx, 16 + i);
            float4 a = __ldg(&P4[(long long)si * 64 + lane]);
            float4 b = __ldg(&P4[(long long)di * 64 + 32 + lane]);
            float4 h;
            h.x = fmaxf(a.x + b.x, 0.f);
            h.y = fmaxf(a.y + b.y, 0.f);
            h.z = fmaxf(a.z + b.z, 0.f);
            h.w = fmaxf(a.w + b.w, 0.f);
            *(float4*)&sH1[(w * 16 + i) * SH1_STRIDE + lane * 4] = h;
        }
        __syncthreads();   // gather complete, previous epilogue reads done

        // ---- GEMM: [128e x 128k] @ [128k x 64o], thread 4e x 8o ----
        unsigned long long acc[4][4];
#pragma unroll
        for (int i = 0; i < 4; i++)
#pragma unroll
            for (int p = 0; p < 4; p++) acc[i][p] = 0ull;

#pragma unroll 8
        for (int dk = 0; dk < 128; dk += 4) {
            float4 hv[4];
#pragma unroll
            for (int i = 0; i < 4; i++)
                hv[i] = *(const float4*)&sH1[(eg * 4 + i) * SH1_STRIDE + dk];
#pragma unroll
            for (int kk = 0; kk < 4; kk++) {
                ulonglong2 w0 = *(const ulonglong2*)&sW2[(dk + kk) * 72 + wcol];
                ulonglong2 w1 = *(const ulonglong2*)&sW2[(dk + kk) * 72 + wcol + 4];
#pragma unroll
                for (int i = 0; i < 4; i++) {
                    float hx = (kk == 0) ? hv[i].x : (kk == 1) ? hv[i].y
                             : (kk == 2) ? hv[i].z : hv[i].w;
                    unsigned long long hh = pack2(hx, hx);
                    fma2(acc[i][0], hh, w0.x);
                    fma2(acc[i][1], hh, w0.y);
                    fma2(acc[i][2], hh, w1.x);
                    fma2(acc[i][3], hh, w1.y);
                }
            }
        }

        // ---- epilogue: +b2, relu, dot W3, reduce over og lanes, store ----
#pragma unroll
        for (int i = 0; i < 4; i++) {
            float v0, v1, v2, v3, v4, v5, v6, v7;
            unpack2(acc[i][0], v0, v1);
            unpack2(acc[i][1], v2, v3);
            unpack2(acc[i][2], v4, v5);
            unpack2(acc[i][3], v6, v7);
            float s = fmaxf(v0 + b2a.x, 0.f) * w3a.x
                    + fmaxf(v1 + b2a.y, 0.f) * w3a.y
                    + fmaxf(v2 + b2a.z, 0.f) * w3a.z
                    + fmaxf(v3 + b2a.w, 0.f) * w3a.w
                    + fmaxf(v4 + b2b.x, 0.f) * w3b.x
                    + fmaxf(v5 + b2b.y, 0.f) * w3b.y
                    + fmaxf(v6 + b2b.z, 0.f) * w3b.z
                    + fmaxf(v7 + b2b.w, 0.f) * w3b.w;
            s += __shfl_xor_sync(0xffffffffu, s, 4);
            s += __shfl_xor_sync(0xffffffffu, s, 2);
            s += __shfl_xor_sync(0xffffffffu, s, 1);
            if (og == 0) {
                int e = t * 128 + eg * 4 + i;
                if (e < E) out[e] = s + bias3;
            }
        }
        __syncthreads();   // GEMM/epilogue reads done before next tile's STS
    }
}

// ---------------------------------------------------------------------------
extern "C" void kernel_launch(void* const* d_in, const int* in_sizes, int n_in,
                              void* d_out, int out_size) {
    const float* emb    = (const float*)d_in[0];
    const int*   eidx_w = (const int*)d_in[1];
    const float* W1     = (const float*)d_in[2];
    const float* b1     = (const float*)d_in[3];
    const float* W2     = (const float*)d_in[4];
    const float* b2     = (const float*)d_in[5];
    const float* W3     = (const float*)d_in[6];
    const float* b3     = (const float*)d_in[7];

    int N = in_sizes[0] / 128;
    int E = in_sizes[1] / 2;
    int nTiles = (E + 127) / 128;

    static int smem_set = 0;
    if (!smem_set) {
        cudaFuncSetAttribute(edge_kernel,
                             cudaFuncAttributeMaxDynamicSharedMemorySize,
                             EDGE_SMEM_BYTES);
        smem_set = 1;
    }

    precompute_kernel<<<(N + 63) / 64, 256>>>(emb, W1, b1, N);
    edge_kernel<<<2 * NSM, 256, EDGE_SMEM_BYTES>>>(eidx_w, W2, b2, W3, b3,
                                                   (float*)d_out, E, N, nTiles);
}

// round 8
// speedup vs baseline: 1.7518x; 1.5826x over previous
#include <cuda_runtime.h>
#include <cuda_bf16.h>
#include <cstdint>

// ---------------------------------------------------------------------------
// LinkWeightDecoder: out[e] = MLP(concat(emb[src_e], emb[dst_e]))
//   K1 (FFMA2): P[n][0:128]=emb@W1[:128]+b1 ; P[n][128:256]=emb@W1[128:]
//   K2 (mma.sync bf16, warp-independent): per 128-edge tile, warp w owns
//     edges w*16..+15: gather h1=relu(Psrc+Pdst) -> bf16 hi/lo in SMEM,
//     D = Ahi·Bhi + Alo·Bhi + Ahi·Blo  (fp32 acc in registers),
//     out[e] = sum_j relu(D[e][j]+b2[j])*W3[j] + b3.
//   No __syncthreads in the tile loop (warps fully independent).
// ---------------------------------------------------------------------------

#define MAXN 100000
#define NSM  148

__device__ float g_P[MAXN * 256];   // per-node projections (102.4 MB)

// ---------------- helpers ----------------
__device__ __forceinline__ unsigned long long pack2(float lo, float hi) {
    unsigned long long r;
    asm("mov.b64 %0, {%1, %2};" : "=l"(r) : "f"(lo), "f"(hi));
    return r;
}
__device__ __forceinline__ void unpack2(unsigned long long v, float& lo, float& hi) {
    asm("mov.b64 {%0, %1}, %2;" : "=f"(lo), "=f"(hi) : "l"(v));
}
__device__ __forceinline__ void fma2(unsigned long long& d,
                                     unsigned long long a, unsigned long long b) {
    asm("fma.rn.f32x2 %0, %1, %2, %0;" : "+l"(d) : "l"(a), "l"(b));
}
__device__ __forceinline__ uint32_t smem_u32(const void* p) {
    uint32_t a;
    asm("{ .reg .u64 t; cvta.to.shared.u64 t, %1; cvt.u32.u64 %0, t; }"
        : "=r"(a) : "l"(p));
    return a;
}
#define SWZ(off) ((off) ^ (((off) >> 3) & 0x70))

__device__ __forceinline__ void ldsm4(uint32_t* r, uint32_t addr) {
    asm volatile("ldmatrix.sync.aligned.m8n8.x4.shared.b16 {%0,%1,%2,%3}, [%4];"
        : "=r"(r[0]), "=r"(r[1]), "=r"(r[2]), "=r"(r[3]) : "r"(addr));
}
__device__ __forceinline__ void ldsm4t(uint32_t* r, uint32_t addr) {
    asm volatile("ldmatrix.sync.aligned.m8n8.x4.trans.shared.b16 {%0,%1,%2,%3}, [%4];"
        : "=r"(r[0]), "=r"(r[1]), "=r"(r[2]), "=r"(r[3]) : "r"(addr));
}
__device__ __forceinline__ void mma16816(float* c, const uint32_t* a,
                                         uint32_t b0, uint32_t b1) {
    asm volatile(
        "mma.sync.aligned.m16n8k16.row.col.f32.bf16.bf16.f32 "
        "{%0,%1,%2,%3}, {%4,%5,%6,%7}, {%8,%9}, {%0,%1,%2,%3};"
        : "+f"(c[0]), "+f"(c[1]), "+f"(c[2]), "+f"(c[3])
        : "r"(a[0]), "r"(a[1]), "r"(a[2]), "r"(a[3]), "r"(b0), "r"(b1));
}

// ---------------------------------------------------------------------------
// Kernel 1: P = emb @ [W1a | W1b]  (FFMA2; unchanged from passing round 6)
// ---------------------------------------------------------------------------
__global__ __launch_bounds__(256, 2)
void precompute_kernel(const float* __restrict__ emb,
                       const float* __restrict__ W1,
                       const float* __restrict__ b1, int N) {
    __shared__ float sW1c[32 * 288];
    __shared__ float sEmb[64 * 33];

    const int tid  = threadIdx.x;
    const int lane = tid & 31, w = tid >> 5;
    const int wx = w & 3, wy = w >> 2;
    const int lx = lane & 7, ly = lane >> 3;
    const int o0  = wx * 64 + lx * 8;
    const int oc0 = o0 + ((o0 >> 5) << 2);
    const int nl0 = wy * 32 + ly * 8;
    const int gn0 = blockIdx.x * 64;

    unsigned long long acc[8][4];
#pragma unroll
    for (int i = 0; i < 8; i++)
#pragma unroll
        for (int p = 0; p < 4; p++) acc[i][p] = 0ull;

    for (int kc = 0; kc < 4; kc++) {
#pragma unroll
        for (int it = 0; it < 2; it++) {
            int slot = it * 256 + tid;
            int node = slot >> 3, kg = slot & 7;
            int gnode = gn0 + node; if (gnode >= N) gnode = N - 1;
            float4 v = *(const float4*)&emb[(long long)gnode * 128 + kc * 32 + kg * 4];
            float* dp = &sEmb[node * 33 + kg * 4];
            dp[0] = v.x; dp[1] = v.y; dp[2] = v.z; dp[3] = v.w;
        }
#pragma unroll
        for (int it = 0; it < 8; it++) {
            int slot = it * 256 + tid;
            int dk = slot >> 6, og = slot & 63;
            int o = og * 4;
            int oc = o + ((o >> 5) << 2);
            int gk = kc * 32 + dk;
            const float* sp = (o < 128) ? &W1[gk * 128 + o]
                                        : &W1[(gk + 128) * 128 + (o - 128)];
            *(float4*)&sW1c[dk * 288 + oc] = *(const float4*)sp;
        }
        __syncthreads();

#pragma unroll
        for (int dk = 0; dk < 32; dk++) {
            const ulonglong2* wp = (const ulonglong2*)&sW1c[dk * 288 + oc0];
            ulonglong2 wa = wp[0], wb = wp[1];
#pragma unroll
            for (int i = 0; i < 8; i++) {
                float ev = sEmb[(nl0 + i) * 33 + dk];
                unsigned long long ee = pack2(ev, ev);
                fma2(acc[i][0], ee, wa.x);
                fma2(acc[i][1], ee, wa.y);
                fma2(acc[i][2], ee, wb.x);
                fma2(acc[i][3], ee, wb.y);
            }
        }
        __syncthreads();
    }

    float bb[8];
#pragma unroll
    for (int j = 0; j < 8; j++) bb[j] = (o0 < 128) ? __ldg(&b1[o0 + j]) : 0.f;

#pragma unroll
    for (int i = 0; i < 8; i++) {
        int gnode = gn0 + nl0 + i;
        if (gnode < N) {
            float v[8];
#pragma unroll
            for (int p = 0; p < 4; p++) unpack2(acc[i][p], v[2 * p], v[2 * p + 1]);
#pragma unroll
            for (int j = 0; j < 8; j++) v[j] += bb[j];
            float4* op = (float4*)&g_P[(long long)gnode * 256 + o0];
            op[0] = make_float4(v[0], v[1], v[2], v[3]);
            op[1] = make_float4(v[4], v[5], v[6], v[7]);
        }
    }
}

// ---------------------------------------------------------------------------
// Kernel 2: persistent, mma.sync bf16 (HMMA), 128-edge tiles, 8 warps.
// SMEM (bytes):
//   A_hi: 2 K-subtiles [128 rows x 64 bf16 = 128B/row, SWZ]  @ 0, 16384
//   A_lo: same                                               @ 32768, 49152
//   B_hi: W2 [128 k rows x 64 n = 128B/row, SWZ]             @ 65536
//   B_lo: same                                               @ 81920
//   sBW4: float4[32] = (b2[2j],W3[2j],b2[2j+1],W3[2j+1])     @ 98304
// ---------------------------------------------------------------------------
#define A_HI_OFF 0
#define A_LO_OFF 32768
#define B_HI_OFF 65536
#define B_LO_OFF 81920
#define SBW_OFF  98304
#define EDGE_SMEM_BYTES (98304 + 512)

__global__ __launch_bounds__(256, 2)
void edge_kernel(const int* __restrict__ eidx_w,
                 const float* __restrict__ W2,
                 const float* __restrict__ b2,
                 const float* __restrict__ W3,
                 const float* __restrict__ b3,
                 float* __restrict__ out, int E, int N, int nTiles) {
    extern __shared__ char smem[];
    const uint32_t sbase = smem_u32(smem);
    float4* sBW4 = (float4*)(smem + SBW_OFF);
    __shared__ int sAny;

    const int tid  = threadIdx.x;
    const int lane = tid & 31, w = tid >> 5;

    // ---- one-time: dtype detect, W2 hi/lo staging, b2/W3 staging ----
    if (tid == 0) sAny = 0;
    __syncthreads();
    if (tid < 64 && eidx_w[2 * tid + 1] != 0) atomicOr(&sAny, 1);

#pragma unroll 4
    for (int it = 0; it < 32; it++) {
        int slot = it * 256 + tid;
        int k = slot >> 6, o = slot & 63;
        float wv = W2[k * 64 + o];
        __nv_bfloat16 hi = __float2bfloat16_rn(wv);
        __nv_bfloat16 lo = __float2bfloat16_rn(wv - __bfloat162float(hi));
        uint32_t off = SWZ((uint32_t)(k * 128 + o * 2));
        *(__nv_bfloat16*)(smem + B_HI_OFF + off) = hi;
        *(__nv_bfloat16*)(smem + B_LO_OFF + off) = lo;
    }
    if (tid < 32)
        sBW4[tid] = make_float4(b2[2 * tid], W3[2 * tid],
                                b2[2 * tid + 1], W3[2 * tid + 1]);
    __syncthreads();

    const int stride = sAny ? 1 : 2;
    const float bias3 = __ldg(&b3[0]);
    const float4* P4 = (const float4*)g_P;
    const int grid = gridDim.x;

    // per-lane ldmatrix addresses (raw byte offsets; SWZ applied per use)
    // A: row = w*16 + (lane&15); halfsel = lane>>4 (16B)
    const int aRow = w * 16 + (lane & 15);
    const int aHalf = (lane >> 4) * 16;
    // B (trans): krow_in_step = (lane&7) + ((lane>>3)&1)*8; nblk half = lane>>4
    const int bKrow = (lane & 7) + ((lane >> 3) & 1) * 8;
    const int bHalf = (lane >> 4) * 16;

    // epilogue mapping
    const int g = lane >> 2, tq = lane & 3;

    for (int t = blockIdx.x; t < nTiles; t += grid) {
        // ---- indices: warp w owns edges t*128 + w*16 .. +15 ----
        int myidx;
        {
            int l = lane & 15;
            int e = t * 128 + w * 16 + l; if (e >= E) e = E - 1;
            long long off = (lane < 16) ? (long long)e * stride
                                        : ((long long)E + e) * stride;
            int v = eidx_w[off];
            myidx = min(max(v, 0), N - 1);
        }

        // ---- gather + relu + bf16 hi/lo -> own 16 A rows ----
#pragma unroll 4
        for (int i = 0; i < 16; i++) {
            int si = __shfl_sync(0xffffffffu, myidx, i);
            int di = __shfl_sync(0xffffffffu, myidx, 16 + i);
            float4 a = __ldg(&P4[(long long)si * 64 + lane]);
            float4 b = __ldg(&P4[(long long)di * 64 + 32 + lane]);
            float4 h;
            h.x = fmaxf(a.x + b.x, 0.f);
            h.y = fmaxf(a.y + b.y, 0.f);
            h.z = fmaxf(a.z + b.z, 0.f);
            h.w = fmaxf(a.w + b.w, 0.f);
            __nv_bfloat162 h01 = __float22bfloat162_rn(make_float2(h.x, h.y));
            __nv_bfloat162 h23 = __float22bfloat162_rn(make_float2(h.z, h.w));
            float2 f01 = __bfloat1622float2(h01);
            float2 f23 = __bfloat1622float2(h23);
            __nv_bfloat162 l01 = __float22bfloat162_rn(make_float2(h.x - f01.x, h.y - f01.y));
            __nv_bfloat162 l23 = __float22bfloat162_rn(make_float2(h.z - f23.x, h.w - f23.y));
            uint2 uhi, ulo;
            uhi.x = *(uint32_t*)&h01; uhi.y = *(uint32_t*)&h23;
            ulo.x = *(uint32_t*)&l01; ulo.y = *(uint32_t*)&l23;

            int row = w * 16 + i;
            int sub = lane >> 4;                       // k-subtile (k<64 / k>=64)
            uint32_t boff = SWZ((uint32_t)(row * 128 + (lane & 15) * 8));
            char* pa = smem + sub * 16384 + boff;
            *(uint2*)(pa + A_HI_OFF) = uhi;
            *(uint2*)(pa + A_LO_OFF) = ulo;
        }
        __syncwarp();   // cross-lane smem visibility for ldmatrix

        // ---- preload Ahi fragments (8 k-steps x 4 regs = 32 regs) ----
        uint32_t Ahi[8][4];
#pragma unroll
        for (int ks = 0; ks < 8; ks++) {
            uint32_t raw = (uint32_t)(aRow * 128 + (ks & 3) * 32 + aHalf);
            ldsm4(Ahi[ks], sbase + A_HI_OFF + (ks >> 2) * 16384 + SWZ(raw));
        }

        float acc[8][4];
#pragma unroll
        for (int nf = 0; nf < 8; nf++)
#pragma unroll
            for (int p = 0; p < 4; p++) acc[nf][p] = 0.f;

        // ---- pass 1+2: Bhi loaded once per kstep; mma Ahi·Bhi + Alo·Bhi ----
#pragma unroll 2
        for (int ks = 0; ks < 8; ks++) {
            uint32_t Alo[4];
            uint32_t rawA = (uint32_t)(aRow * 128 + (ks & 3) * 32 + aHalf);
            ldsm4(Alo, sbase + A_LO_OFF + (ks >> 2) * 16384 + SWZ(rawA));
#pragma unroll
            for (int nb = 0; nb < 4; nb++) {
                uint32_t bfr[4];
                uint32_t rawB = (uint32_t)((ks * 16 + bKrow) * 128 + nb * 32 + bHalf);
                ldsm4t(bfr, sbase + B_HI_OFF + SWZ(rawB));
                mma16816(acc[2 * nb],     Ahi[ks], bfr[0], bfr[1]);
                mma16816(acc[2 * nb + 1], Ahi[ks], bfr[2], bfr[3]);
                mma16816(acc[2 * nb],     Alo,     bfr[0], bfr[1]);
                mma16816(acc[2 * nb + 1], Alo,     bfr[2], bfr[3]);
            }
        }
        // ---- pass 3: Ahi·Blo ----
#pragma unroll 2
        for (int ks = 0; ks < 8; ks++) {
#pragma unroll
            for (int nb = 0; nb < 4; nb++) {
                uint32_t bfr[4];
                uint32_t rawB = (uint32_t)((ks * 16 + bKrow) * 128 + nb * 32 + bHalf);
                ldsm4t(bfr, sbase + B_LO_OFF + SWZ(rawB));
                mma16816(acc[2 * nb],     Ahi[ks], bfr[0], bfr[1]);
                mma16816(acc[2 * nb + 1], Ahi[ks], bfr[2], bfr[3]);
            }
        }

        // ---- epilogue: thread holds D[e0+g][c],D[e0+g][c+1],D[e0+g+8][*] ----
        float s1 = 0.f, s2 = 0.f;
#pragma unroll
        for (int nf = 0; nf < 8; nf++) {
            float4 bw = sBW4[nf * 4 + tq];   // (b2[c], W3[c], b2[c+1], W3[c+1])
            s1 += fmaxf(acc[nf][0] + bw.x, 0.f) * bw.y
                + fmaxf(acc[nf][1] + bw.z, 0.f) * bw.w;
            s2 += fmaxf(acc[nf][2] + bw.x, 0.f) * bw.y
                + fmaxf(acc[nf][3] + bw.z, 0.f) * bw.w;
        }
        s1 += __shfl_xor_sync(0xffffffffu, s1, 1);
        s1 += __shfl_xor_sync(0xffffffffu, s1, 2);
        s2 += __shfl_xor_sync(0xffffffffu, s2, 1);
        s2 += __shfl_xor_sync(0xffffffffu, s2, 2);
        if (tq == 0) {
            int e1 = t * 128 + w * 16 + g;
            int e2 = e1 + 8;
            if (e1 < E) out[e1] = s1 + bias3;
            if (e2 < E) out[e2] = s2 + bias3;
        }
        __syncwarp();   // epilogue/A reads done before next tile's STS
    }
}

// ---------------------------------------------------------------------------
extern "C" void kernel_launch(void* const* d_in, const int* in_sizes, int n_in,
                              void* d_out, int out_size) {
    const float* emb    = (const float*)d_in[0];
    const int*   eidx_w = (const int*)d_in[1];
    const float* W1     = (const float*)d_in[2];
    const float* b1     = (const float*)d_in[3];
    const float* W2     = (const float*)d_in[4];
    const float* b2     = (const float*)d_in[5];
    const float* W3     = (const float*)d_in[6];
    const float* b3     = (const float*)d_in[7];

    int N = in_sizes[0] / 128;
    int E = in_sizes[1] / 2;
    int nTiles = (E + 127) / 128;

    static int smem_set = 0;
    if (!smem_set) {
        cudaFuncSetAttribute(edge_kernel,
                             cudaFuncAttributeMaxDynamicSharedMemorySize,
                             EDGE_SMEM_BYTES);
        smem_set = 1;
    }

    precompute_kernel<<<(N + 63) / 64, 256>>>(emb, W1, b1, N);
    edge_kernel<<<2 * NSM, 256, EDGE_SMEM_BYTES>>>(eidx_w, W2, b2, W3, b3,
                                                   (float*)d_out, E, N, nTiles);
}

// round 9
// speedup vs baseline: 2.1087x; 1.2037x over previous
#include <cuda_runtime.h>
#include <cuda_bf16.h>
#include <cstdint>

// ---------------------------------------------------------------------------
// LinkWeightDecoder: out[e] = MLP(concat(emb[src_e], emb[dst_e]))
//   K1 (mma.sync bf16 hi/lo): P[n][0:256] = emb[n] @ [W1a|W1b] (+b1 on first half)
//   K2 (mma.sync bf16 hi/lo): per 128-edge tile, warp-independent:
//     gather h1=relu(Psrc+Pdst) -> bf16 hi/lo, D = 3-pass bf16 GEMM vs W2,
//     out[e] = sum_j relu(D[e][j]+b2[j])*W3[j] + b3.
// ---------------------------------------------------------------------------

#define MAXN 100000
#define NSM  148

__device__ float g_P[MAXN * 256];   // per-node projections (102.4 MB)

// ---------------- helpers ----------------
__device__ __forceinline__ uint32_t smem_u32(const void* p) {
    uint32_t a;
    asm("{ .reg .u64 t; cvta.to.shared.u64 t, %1; cvt.u32.u64 %0, t; }"
        : "=r"(a) : "l"(p));
    return a;
}
#define SWZ(off) ((off) ^ (((off) >> 3) & 0x70))

__device__ __forceinline__ void ldsm4(uint32_t* r, uint32_t addr) {
    asm volatile("ldmatrix.sync.aligned.m8n8.x4.shared.b16 {%0,%1,%2,%3}, [%4];"
        : "=r"(r[0]), "=r"(r[1]), "=r"(r[2]), "=r"(r[3]) : "r"(addr));
}
__device__ __forceinline__ void ldsm4t(uint32_t* r, uint32_t addr) {
    asm volatile("ldmatrix.sync.aligned.m8n8.x4.trans.shared.b16 {%0,%1,%2,%3}, [%4];"
        : "=r"(r[0]), "=r"(r[1]), "=r"(r[2]), "=r"(r[3]) : "r"(addr));
}
__device__ __forceinline__ void mma16816(float* c, const uint32_t* a,
                                         uint32_t b0, uint32_t b1) {
    asm volatile(
        "mma.sync.aligned.m16n8k16.row.col.f32.bf16.bf16.f32 "
        "{%0,%1,%2,%3}, {%4,%5,%6,%7}, {%8,%9}, {%0,%1,%2,%3};"
        : "+f"(c[0]), "+f"(c[1]), "+f"(c[2]), "+f"(c[3])
        : "r"(a[0]), "r"(a[1]), "r"(a[2]), "r"(a[3]), "r"(b0), "r"(b1));
}
// split fp32 quad -> bf16 hi/lo packed uint2
__device__ __forceinline__ void split4(float4 h, uint2& uhi, uint2& ulo) {
    __nv_bfloat162 h01 = __float22bfloat162_rn(make_float2(h.x, h.y));
    __nv_bfloat162 h23 = __float22bfloat162_rn(make_float2(h.z, h.w));
    float2 f01 = __bfloat1622float2(h01);
    float2 f23 = __bfloat1622float2(h23);
    __nv_bfloat162 l01 = __float22bfloat162_rn(make_float2(h.x - f01.x, h.y - f01.y));
    __nv_bfloat162 l23 = __float22bfloat162_rn(make_float2(h.z - f23.x, h.w - f23.y));
    uhi.x = *(uint32_t*)&h01; uhi.y = *(uint32_t*)&h23;
    ulo.x = *(uint32_t*)&l01; ulo.y = *(uint32_t*)&l23;
}

// ---------------------------------------------------------------------------
// Kernel 1 (persistent, HMMA): P = emb @ [W1a|W1b] (+b1 fold on cols<128)
// SMEM (bytes):
//   A_hi/A_lo: [128 rows x 128 k bf16], 2 K-subtiles each   @ 0 / 32768
//   B_hi/B_lo: W1eff [128k x 256n] as 4 chunk-tiles of
//              [128k x 64n, 128B/row, SWZ]                  @ 65536 / 131072
//   sB1: float[256] (b1 for o<128 else 0)                   @ 196608
// ---------------------------------------------------------------------------
#define PA_HI 0
#define PA_LO 32768
#define PB_HI 65536
#define PB_LO 131072
#define PB1   196608
#define PRE_SMEM_BYTES (196608 + 1024)

__global__ __launch_bounds__(256, 1)
void precompute_kernel(const float* __restrict__ emb,
                       const float* __restrict__ W1,
                       const float* __restrict__ b1, int N, int nTiles) {
    extern __shared__ char smem[];
    const uint32_t sbase = smem_u32(smem);
    float* sB1 = (float*)(smem + PB1);

    const int tid  = threadIdx.x;
    const int lane = tid & 31, w = tid >> 5;

    // ---- one-time: stage W1eff hi/lo (4 chunk-tiles), sB1 ----
#pragma unroll 4
    for (int it = 0; it < 32; it++) {
        int idx = it * 256 + tid;          // 8192 float4 slots
        int k = idx >> 6, og4 = (idx & 63) * 4;
        const float* sp = (og4 < 128) ? &W1[k * 128 + og4]
                                      : &W1[(k + 128) * 128 + (og4 - 128)];
        float4 v = *(const float4*)sp;
        uint2 uhi, ulo;
        split4(v, uhi, ulo);
        int c = og4 >> 6, o = og4 & 63;
        uint32_t off = c * 16384 + SWZ((uint32_t)(k * 128 + o * 2));
        *(uint2*)(smem + PB_HI + off) = uhi;
        *(uint2*)(smem + PB_LO + off) = ulo;
    }
    sB1[tid] = (tid < 128) ? b1[tid] : 0.f;
    __syncthreads();

    // ldmatrix lane addressing (same mapping as edge kernel)
    const int aRow  = w * 16 + (lane & 15);
    const int aHalf = (lane >> 4) * 16;
    const int bKrow = (lane & 7) + ((lane >> 3) & 1) * 8;
    const int bHalf = (lane >> 4) * 16;
    const int g = lane >> 2, tq = lane & 3;

    const float4* E4 = (const float4*)emb;
    const int grid = gridDim.x;

    for (int t = blockIdx.x; t < nTiles; t += grid) {
        // ---- stage own 16 A rows (emb fp32 -> bf16 hi/lo) ----
#pragma unroll 4
        for (int i = 0; i < 16; i++) {
            int row = w * 16 + i;
            int node = t * 128 + row; if (node >= N) node = N - 1;
            float4 v = __ldg(&E4[(long long)node * 32 + lane]);
            uint2 uhi, ulo;
            split4(v, uhi, ulo);
            int sub = lane >> 4;
            uint32_t boff = SWZ((uint32_t)(row * 128 + (lane & 15) * 8));
            char* pa = smem + sub * 16384 + boff;
            *(uint2*)(pa + PA_HI) = uhi;
            *(uint2*)(pa + PA_LO) = ulo;
        }
        __syncwarp();

        // ---- 4 n-chunks of 64 cols, each identical to the edge GEMM ----
#pragma unroll 1
        for (int c = 0; c < 4; c++) {
            const uint32_t bHi = sbase + PB_HI + c * 16384;
            const uint32_t bLo = sbase + PB_LO + c * 16384;

            uint32_t Ahi[8][4];
#pragma unroll
            for (int ks = 0; ks < 8; ks++) {
                uint32_t raw = (uint32_t)(aRow * 128 + (ks & 3) * 32 + aHalf);
                ldsm4(Ahi[ks], sbase + PA_HI + (ks >> 2) * 16384 + SWZ(raw));
            }

            float acc[8][4];
#pragma unroll
            for (int nf = 0; nf < 8; nf++)
#pragma unroll
                for (int p = 0; p < 4; p++) acc[nf][p] = 0.f;

#pragma unroll 2
            for (int ks = 0; ks < 8; ks++) {
                uint32_t Alo[4];
                uint32_t rawA = (uint32_t)(aRow * 128 + (ks & 3) * 32 + aHalf);
                ldsm4(Alo, sbase + PA_LO + (ks >> 2) * 16384 + SWZ(rawA));
#pragma unroll
                for (int nb = 0; nb < 4; nb++) {
                    uint32_t bfr[4];
                    uint32_t rawB = (uint32_t)((ks * 16 + bKrow) * 128 + nb * 32 + bHalf);
                    ldsm4t(bfr, bHi + SWZ(rawB));
                    mma16816(acc[2 * nb],     Ahi[ks], bfr[0], bfr[1]);
                    mma16816(acc[2 * nb + 1], Ahi[ks], bfr[2], bfr[3]);
                    mma16816(acc[2 * nb],     Alo,     bfr[0], bfr[1]);
                    mma16816(acc[2 * nb + 1], Alo,     bfr[2], bfr[3]);
                }
            }
#pragma unroll 2
            for (int ks = 0; ks < 8; ks++) {
#pragma unroll
                for (int nb = 0; nb < 4; nb++) {
                    uint32_t bfr[4];
                    uint32_t rawB = (uint32_t)((ks * 16 + bKrow) * 128 + nb * 32 + bHalf);
                    ldsm4t(bfr, bLo + SWZ(rawB));
                    mma16816(acc[2 * nb],     Ahi[ks], bfr[0], bfr[1]);
                    mma16816(acc[2 * nb + 1], Ahi[ks], bfr[2], bfr[3]);
                }
            }

            // ---- epilogue: +b1 (cols<128), store fp32 pairs to g_P ----
            int n1 = t * 128 + w * 16 + g;
            int n2 = n1 + 8;
#pragma unroll
            for (int nf = 0; nf < 8; nf++) {
                int o = c * 64 + nf * 8 + tq * 2;
                float2 bias = *(const float2*)&sB1[o];
                if (n1 < N) {
                    float2 r = make_float2(acc[nf][0] + bias.x, acc[nf][1] + bias.y);
                    *(float2*)&g_P[(long long)n1 * 256 + o] = r;
                }
                if (n2 < N) {
                    float2 r = make_float2(acc[nf][2] + bias.x, acc[nf][3] + bias.y);
                    *(float2*)&g_P[(long long)n2 * 256 + o] = r;
                }
            }
        }
        __syncwarp();   // own A-tile reads done before next tile's stores
    }
}

// ---------------------------------------------------------------------------
// Kernel 2: persistent, mma.sync bf16 (HMMA), 128-edge tiles, 8 warps.
// (unchanged from passing round 8)
// ---------------------------------------------------------------------------
#define A_HI_OFF 0
#define A_LO_OFF 32768
#define B_HI_OFF 65536
#define B_LO_OFF 81920
#define SBW_OFF  98304
#define EDGE_SMEM_BYTES (98304 + 512)

__global__ __launch_bounds__(256, 2)
void edge_kernel(const int* __restrict__ eidx_w,
                 const float* __restrict__ W2,
                 const float* __restrict__ b2,
                 const float* __restrict__ W3,
                 const float* __restrict__ b3,
                 float* __restrict__ out, int E, int N, int nTiles) {
    extern __shared__ char smem[];
    const uint32_t sbase = smem_u32(smem);
    float4* sBW4 = (float4*)(smem + SBW_OFF);
    __shared__ int sAny;

    const int tid  = threadIdx.x;
    const int lane = tid & 31, w = tid >> 5;

    if (tid == 0) sAny = 0;
    __syncthreads();
    if (tid < 64 && eidx_w[2 * tid + 1] != 0) atomicOr(&sAny, 1);

#pragma unroll 4
    for (int it = 0; it < 32; it++) {
        int slot = it * 256 + tid;
        int k = slot >> 6, o = slot & 63;
        float wv = W2[k * 64 + o];
        __nv_bfloat16 hi = __float2bfloat16_rn(wv);
        __nv_bfloat16 lo = __float2bfloat16_rn(wv - __bfloat162float(hi));
        uint32_t off = SWZ((uint32_t)(k * 128 + o * 2));
        *(__nv_bfloat16*)(smem + B_HI_OFF + off) = hi;
        *(__nv_bfloat16*)(smem + B_LO_OFF + off) = lo;
    }
    if (tid < 32)
        sBW4[tid] = make_float4(b2[2 * tid], W3[2 * tid],
                                b2[2 * tid + 1], W3[2 * tid + 1]);
    __syncthreads();

    const int stride = sAny ? 1 : 2;
    const float bias3 = __ldg(&b3[0]);
    const float4* P4 = (const float4*)g_P;
    const int grid = gridDim.x;

    const int aRow = w * 16 + (lane & 15);
    const int aHalf = (lane >> 4) * 16;
    const int bKrow = (lane & 7) + ((lane >> 3) & 1) * 8;
    const int bHalf = (lane >> 4) * 16;
    const int g = lane >> 2, tq = lane & 3;

    for (int t = blockIdx.x; t < nTiles; t += grid) {
        int myidx;
        {
            int l = lane & 15;
            int e = t * 128 + w * 16 + l; if (e >= E) e = E - 1;
            long long off = (lane < 16) ? (long long)e * stride
                                        : ((long long)E + e) * stride;
            int v = eidx_w[off];
            myidx = min(max(v, 0), N - 1);
        }

#pragma unroll 4
        for (int i = 0; i < 16; i++) {
            int si = __shfl_sync(0xffffffffu, myidx, i);
            int di = __shfl_sync(0xffffffffu, myidx, 16 + i);
            float4 a = __ldg(&P4[(long long)si * 64 + lane]);
            float4 b = __ldg(&P4[(long long)di * 64 + 32 + lane]);
            float4 h;
            h.x = fmaxf(a.x + b.x, 0.f);
            h.y = fmaxf(a.y + b.y, 0.f);
            h.z = fmaxf(a.z + b.z, 0.f);
            h.w = fmaxf(a.w + b.w, 0.f);
            uint2 uhi, ulo;
            split4(h, uhi, ulo);

            int row = w * 16 + i;
            int sub = lane >> 4;
            uint32_t boff = SWZ((uint32_t)(row * 128 + (lane & 15) * 8));
            char* pa = smem + sub * 16384 + boff;
            *(uint2*)(pa + A_HI_OFF) = uhi;
            *(uint2*)(pa + A_LO_OFF) = ulo;
        }
        __syncwarp();

        uint32_t Ahi[8][4];
#pragma unroll
        for (int ks = 0; ks < 8; ks++) {
            uint32_t raw = (uint32_t)(aRow * 128 + (ks & 3) * 32 + aHalf);
            ldsm4(Ahi[ks], sbase + A_HI_OFF + (ks >> 2) * 16384 + SWZ(raw));
        }

        float acc[8][4];
#pragma unroll
        for (int nf = 0; nf < 8; nf++)
#pragma unroll
            for (int p = 0; p < 4; p++) acc[nf][p] = 0.f;

#pragma unroll 2
        for (int ks = 0; ks < 8; ks++) {
            uint32_t Alo[4];
            uint32_t rawA = (uint32_t)(aRow * 128 + (ks & 3) * 32 + aHalf);
            ldsm4(Alo, sbase + A_LO_OFF + (ks >> 2) * 16384 + SWZ(rawA));
#pragma unroll
            for (int nb = 0; nb < 4; nb++) {
                uint32_t bfr[4];
                uint32_t rawB = (uint32_t)((ks * 16 + bKrow) * 128 + nb * 32 + bHalf);
                ldsm4t(bfr, sbase + B_HI_OFF + SWZ(rawB));
                mma16816(acc[2 * nb],     Ahi[ks], bfr[0], bfr[1]);
                mma16816(acc[2 * nb + 1], Ahi[ks], bfr[2], bfr[3]);
                mma16816(acc[2 * nb],     Alo,     bfr[0], bfr[1]);
                mma16816(acc[2 * nb + 1], Alo,     bfr[2], bfr[3]);
            }
        }
#pragma unroll 2
        for (int ks = 0; ks < 8; ks++) {
#pragma unroll
            for (int nb = 0; nb < 4; nb++) {
                uint32_t bfr[4];
                uint32_t rawB = (uint32_t)((ks * 16 + bKrow) * 128 + nb * 32 + bHalf);
                ldsm4t(bfr, sbase + B_LO_OFF + SWZ(rawB));
                mma16816(acc[2 * nb],     Ahi[ks], bfr[0], bfr[1]);
                mma16816(acc[2 * nb + 1], Ahi[ks], bfr[2], bfr[3]);
            }
        }

        float s1 = 0.f, s2 = 0.f;
#pragma unroll
        for (int nf = 0; nf < 8; nf++) {
            float4 bw = sBW4[nf * 4 + tq];
            s1 += fmaxf(acc[nf][0] + bw.x, 0.f) * bw.y
                + fmaxf(acc[nf][1] + bw.z, 0.f) * bw.w;
            s2 += fmaxf(acc[nf][2] + bw.x, 0.f) * bw.y
                + fmaxf(acc[nf][3] + bw.z, 0.f) * bw.w;
        }
        s1 += __shfl_xor_sync(0xffffffffu, s1, 1);
        s1 += __shfl_xor_sync(0xffffffffu, s1, 2);
        s2 += __shfl_xor_sync(0xffffffffu, s2, 1);
        s2 += __shfl_xor_sync(0xffffffffu, s2, 2);
        if (tq == 0) {
            int e1 = t * 128 + w * 16 + g;
            int e2 = e1 + 8;
            if (e1 < E) out[e1] = s1 + bias3;
            if (e2 < E) out[e2] = s2 + bias3;
        }
        __syncwarp();
    }
}

// ---------------------------------------------------------------------------
extern "C" void kernel_launch(void* const* d_in, const int* in_sizes, int n_in,
                              void* d_out, int out_size) {
    const float* emb    = (const float*)d_in[0];
    const int*   eidx_w = (const int*)d_in[1];
    const float* W1     = (const float*)d_in[2];
    const float* b1     = (const float*)d_in[3];
    const float* W2     = (const float*)d_in[4];
    const float* b2     = (const float*)d_in[5];
    const float* W3     = (const float*)d_in[6];
    const float* b3     = (const float*)d_in[7];

    int N = in_sizes[0] / 128;
    int E = in_sizes[1] / 2;
    int nTilesP = (N + 127) / 128;
    int nTilesE = (E + 127) / 128;

    static int smem_set = 0;
    if (!smem_set) {
        cudaFuncSetAttribute(precompute_kernel,
                             cudaFuncAttributeMaxDynamicSharedMemorySize,
                             PRE_SMEM_BYTES);
        cudaFuncSetAttribute(edge_kernel,
                             cudaFuncAttributeMaxDynamicSharedMemorySize,
                             EDGE_SMEM_BYTES);
        smem_set = 1;
    }

    precompute_kernel<<<NSM, 256, PRE_SMEM_BYTES>>>(emb, W1, b1, N, nTilesP);
    edge_kernel<<<2 * NSM, 256, EDGE_SMEM_BYTES>>>(eidx_w, W2, b2, W3, b3,
                                                   (float*)d_out, E, N, nTilesE);
}

// round 10
// speedup vs baseline: 2.3167x; 1.0987x over previous
#include <cuda_runtime.h>
#include <cuda_bf16.h>
#include <cstdint>

// ---------------------------------------------------------------------------
// LinkWeightDecoder: out[e] = MLP(concat(emb[src_e], emb[dst_e]))
//   K1 (mma.sync bf16 hi/lo): P[n][0:256] = emb[n] @ [W1a|W1b] (+b1 on first half)
//   K2 (mma.sync bf16 hi/lo): per 128-edge tile, warp-independent:
//     gather h1=relu(Psrc+Pdst) -> bf16 hi/lo, D = 3-pass bf16 GEMM vs W2
//     (passes fused in one k loop), out[e]=sum_j relu(D[e][j]+b2[j])*W3[j]+b3.
//   Edge kernel uses XOR-compressed precomputed ldmatrix addresses.
// ---------------------------------------------------------------------------

#define MAXN 100000
#define NSM  148

__device__ float g_P[MAXN * 256];   // per-node projections (102.4 MB)

// ---------------- helpers ----------------
__device__ __forceinline__ uint32_t smem_u32(const void* p) {
    uint32_t a;
    asm("{ .reg .u64 t; cvta.to.shared.u64 t, %1; cvt.u32.u64 %0, t; }"
        : "=r"(a) : "l"(p));
    return a;
}
#define SWZ(off) ((off) ^ (((off) >> 3) & 0x70))

__device__ __forceinline__ void ldsm4(uint32_t* r, uint32_t addr) {
    asm volatile("ldmatrix.sync.aligned.m8n8.x4.shared.b16 {%0,%1,%2,%3}, [%4];"
        : "=r"(r[0]), "=r"(r[1]), "=r"(r[2]), "=r"(r[3]) : "r"(addr));
}
__device__ __forceinline__ void ldsm4t(uint32_t* r, uint32_t addr) {
    asm volatile("ldmatrix.sync.aligned.m8n8.x4.trans.shared.b16 {%0,%1,%2,%3}, [%4];"
        : "=r"(r[0]), "=r"(r[1]), "=r"(r[2]), "=r"(r[3]) : "r"(addr));
}
__device__ __forceinline__ void mma16816(float* c, const uint32_t* a,
                                         uint32_t b0, uint32_t b1) {
    asm volatile(
        "mma.sync.aligned.m16n8k16.row.col.f32.bf16.bf16.f32 "
        "{%0,%1,%2,%3}, {%4,%5,%6,%7}, {%8,%9}, {%0,%1,%2,%3};"
        : "+f"(c[0]), "+f"(c[1]), "+f"(c[2]), "+f"(c[3])
        : "r"(a[0]), "r"(a[1]), "r"(a[2]), "r"(a[3]), "r"(b0), "r"(b1));
}
// split fp32 quad -> bf16 hi/lo packed uint2
__device__ __forceinline__ void split4(float4 h, uint2& uhi, uint2& ulo) {
    __nv_bfloat162 h01 = __float22bfloat162_rn(make_float2(h.x, h.y));
    __nv_bfloat162 h23 = __float22bfloat162_rn(make_float2(h.z, h.w));
    float2 f01 = __bfloat1622float2(h01);
    float2 f23 = __bfloat1622float2(h23);
    __nv_bfloat162 l01 = __float22bfloat162_rn(make_float2(h.x - f01.x, h.y - f01.y));
    __nv_bfloat162 l23 = __float22bfloat162_rn(make_float2(h.z - f23.x, h.w - f23.y));
    uhi.x = *(uint32_t*)&h01; uhi.y = *(uint32_t*)&h23;
    ulo.x = *(uint32_t*)&l01; ulo.y = *(uint32_t*)&l23;
}

// ---------------------------------------------------------------------------
// Kernel 1 (persistent, HMMA): P = emb @ [W1a|W1b] (+b1 fold on cols<128)
// (unchanged from passing round 9)
// ---------------------------------------------------------------------------
#define PA_HI 0
#define PA_LO 32768
#define PB_HI 65536
#define PB_LO 131072
#define PB1   196608
#define PRE_SMEM_BYTES (196608 + 1024)

__global__ __launch_bounds__(256, 1)
void precompute_kernel(const float* __restrict__ emb,
                       const float* __restrict__ W1,
                       const float* __restrict__ b1, int N, int nTiles) {
    extern __shared__ char smem[];
    const uint32_t sbase = smem_u32(smem);
    float* sB1 = (float*)(smem + PB1);

    const int tid  = threadIdx.x;
    const int lane = tid & 31, w = tid >> 5;

#pragma unroll 4
    for (int it = 0; it < 32; it++) {
        int idx = it * 256 + tid;
        int k = idx >> 6, og4 = (idx & 63) * 4;
        const float* sp = (og4 < 128) ? &W1[k * 128 + og4]
                                      : &W1[(k + 128) * 128 + (og4 - 128)];
        float4 v = *(const float4*)sp;
        uint2 uhi, ulo;
        split4(v, uhi, ulo);
        int c = og4 >> 6, o = og4 & 63;
        uint32_t off = c * 16384 + SWZ((uint32_t)(k * 128 + o * 2));
        *(uint2*)(smem + PB_HI + off) = uhi;
        *(uint2*)(smem + PB_LO + off) = ulo;
    }
    sB1[tid] = (tid < 128) ? b1[tid] : 0.f;
    __syncthreads();

    const int aRow  = w * 16 + (lane & 15);
    const int aHalf = (lane >> 4) * 16;
    const int bKrow = (lane & 7) + ((lane >> 3) & 1) * 8;
    const int bHalf = (lane >> 4) * 16;
    const int g = lane >> 2, tq = lane & 3;

    const float4* E4 = (const float4*)emb;
    const int grid = gridDim.x;

    for (int t = blockIdx.x; t < nTiles; t += grid) {
#pragma unroll 4
        for (int i = 0; i < 16; i++) {
            int row = w * 16 + i;
            int node = t * 128 + row; if (node >= N) node = N - 1;
            float4 v = __ldg(&E4[(long long)node * 32 + lane]);
            uint2 uhi, ulo;
            split4(v, uhi, ulo);
            int sub = lane >> 4;
            uint32_t boff = SWZ((uint32_t)(row * 128 + (lane & 15) * 8));
            char* pa = smem + sub * 16384 + boff;
            *(uint2*)(pa + PA_HI) = uhi;
            *(uint2*)(pa + PA_LO) = ulo;
        }
        __syncwarp();

#pragma unroll 1
        for (int c = 0; c < 4; c++) {
            const uint32_t bHi = sbase + PB_HI + c * 16384;
            const uint32_t bLo = sbase + PB_LO + c * 16384;

            uint32_t Ahi[8][4];
#pragma unroll
            for (int ks = 0; ks < 8; ks++) {
                uint32_t raw = (uint32_t)(aRow * 128 + (ks & 3) * 32 + aHalf);
                ldsm4(Ahi[ks], sbase + PA_HI + (ks >> 2) * 16384 + SWZ(raw));
            }

            float acc[8][4];
#pragma unroll
            for (int nf = 0; nf < 8; nf++)
#pragma unroll
                for (int p = 0; p < 4; p++) acc[nf][p] = 0.f;

#pragma unroll 2
            for (int ks = 0; ks < 8; ks++) {
                uint32_t Alo[4];
                uint32_t rawA = (uint32_t)(aRow * 128 + (ks & 3) * 32 + aHalf);
                ldsm4(Alo, sbase + PA_LO + (ks >> 2) * 16384 + SWZ(rawA));
#pragma unroll
                for (int nb = 0; nb < 4; nb++) {
                    uint32_t bfr[4];
                    uint32_t rawB = (uint32_t)((ks * 16 + bKrow) * 128 + nb * 32 + bHalf);
                    ldsm4t(bfr, bHi + SWZ(rawB));
                    mma16816(acc[2 * nb],     Ahi[ks], bfr[0], bfr[1]);
                    mma16816(acc[2 * nb + 1], Ahi[ks], bfr[2], bfr[3]);
                    mma16816(acc[2 * nb],     Alo,     bfr[0], bfr[1]);
                    mma16816(acc[2 * nb + 1], Alo,     bfr[2], bfr[3]);
                }
            }
#pragma unroll 2
            for (int ks = 0; ks < 8; ks++) {
#pragma unroll
                for (int nb = 0; nb < 4; nb++) {
                    uint32_t bfr[4];
                    uint32_t rawB = (uint32_t)((ks * 16 + bKrow) * 128 + nb * 32 + bHalf);
                    ldsm4t(bfr, bLo + SWZ(rawB));
                    mma16816(acc[2 * nb],     Ahi[ks], bfr[0], bfr[1]);
                    mma16816(acc[2 * nb + 1], Ahi[ks], bfr[2], bfr[3]);
                }
            }

            int n1 = t * 128 + w * 16 + g;
            int n2 = n1 + 8;
#pragma unroll
            for (int nf = 0; nf < 8; nf++) {
                int o = c * 64 + nf * 8 + tq * 2;
                float2 bias = *(const float2*)&sB1[o];
                if (n1 < N) {
                    float2 r = make_float2(acc[nf][0] + bias.x, acc[nf][1] + bias.y);
                    *(float2*)&g_P[(long long)n1 * 256 + o] = r;
                }
                if (n2 < N) {
                    float2 r = make_float2(acc[nf][2] + bias.x, acc[nf][3] + bias.y);
                    *(float2*)&g_P[(long long)n2 * 256 + o] = r;
                }
            }
        }
        __syncwarp();
    }
}

// ---------------------------------------------------------------------------
// Kernel 2: persistent HMMA, 128-edge tiles, 8 independent warps.
// Fused 3-pass loop + XOR-compressed precomputed ldmatrix addresses.
// Smem base manually aligned to 1024 (required by the XOR address algebra).
// ---------------------------------------------------------------------------
#define A_HI_OFF 0
#define A_LO_OFF 32768
#define B_HI_OFF 65536
#define B_LO_OFF 81920
#define SBW_OFF  98304
#define EDGE_SMEM_BYTES (98304 + 512 + 1024)

__global__ __launch_bounds__(256, 2)
void edge_kernel(const int* __restrict__ eidx_w,
                 const float* __restrict__ W2,
                 const float* __restrict__ b2,
                 const float* __restrict__ W3,
                 const float* __restrict__ b3,
                 float* __restrict__ out, int E, int N, int nTiles) {
    extern __shared__ char smem_raw[];
    char* sm = (char*)(((uintptr_t)smem_raw + 1023) & ~(uintptr_t)1023);
    const uint32_t sbase = smem_u32(sm);
    float4* sBW4 = (float4*)(sm + SBW_OFF);
    __shared__ int sAny;

    const int tid  = threadIdx.x;
    const int lane = tid & 31, w = tid >> 5;

    // ---- one-time: dtype detect, W2 hi/lo staging, b2/W3 staging ----
    if (tid == 0) sAny = 0;
    __syncthreads();
    if (tid < 64 && eidx_w[2 * tid + 1] != 0) atomicOr(&sAny, 1);

#pragma unroll 4
    for (int it = 0; it < 32; it++) {
        int slot = it * 256 + tid;
        int k = slot >> 6, o = slot & 63;
        float wv = W2[k * 64 + o];
        __nv_bfloat16 hi = __float2bfloat16_rn(wv);
        __nv_bfloat16 lo = __float2bfloat16_rn(wv - __bfloat162float(hi));
        uint32_t off = SWZ((uint32_t)(k * 128 + o * 2));
        *(__nv_bfloat16*)(sm + B_HI_OFF + off) = hi;
        *(__nv_bfloat16*)(sm + B_LO_OFF + off) = lo;
    }
    if (tid < 32)
        sBW4[tid] = make_float4(b2[2 * tid], W3[2 * tid],
                                b2[2 * tid + 1], W3[2 * tid + 1]);
    __syncthreads();

    const int stride = sAny ? 1 : 2;
    const float bias3 = __ldg(&b3[0]);
    const float4* P4 = (const float4*)g_P;
    const int grid = gridDim.x;

    // ---- lane-invariant fragment geometry ----
    const int aRow  = w * 16 + (lane & 15);
    const int aHalf = (lane >> 4) * 16;
    const int bKrow = (lane & 7) + ((lane >> 3) & 1) * 8;
    const int bHalf = (lane >> 4) * 16;
    const int g = lane >> 2, tq = lane & 3;

    // ---- XOR-compressed ldmatrix base addresses (loop-invariant) ----
    // A: addrAhi(ks) = (aBaseHi + (ks>>2)*16384) ^ ((ks&3)<<5); Alo = +32768
    const uint32_t Ra = (uint32_t)(aRow * 128);
    const uint32_t aBaseHi = sbase + A_HI_OFF + Ra
                           + ((uint32_t)aHalf ^ ((Ra >> 3) & 0x70));
    // B: addrBhi(ks,nb) = bBase[ks] ^ (nb<<5); Blo = +16384
    uint32_t bBase[8];
#pragma unroll
    for (int ks = 0; ks < 8; ks++) {
        uint32_t Rb = (uint32_t)((ks * 16 + bKrow) * 128);
        bBase[ks] = sbase + B_HI_OFF + Rb
                  + ((uint32_t)bHalf ^ ((Rb >> 3) & 0x70));
    }

    // index loader (warp w owns edges t*128 + w*16 .. +15)
    auto load_idx = [&](int t) -> int {
        int l = lane & 15;
        int e = t * 128 + w * 16 + l; if (e >= E) e = E - 1;
        long long off = (lane < 16) ? (long long)e * stride
                                    : ((long long)E + e) * stride;
        int v = eidx_w[off];
        return min(max(v, 0), N - 1);
    };

    int t = blockIdx.x;
    int myidx = (t < nTiles) ? load_idx(t) : 0;

    for (; t < nTiles; t += grid) {
        // ---- gather + relu + bf16 hi/lo -> own 16 A rows ----
#pragma unroll 4
        for (int i = 0; i < 16; i++) {
            int si = __shfl_sync(0xffffffffu, myidx, i);
            int di = __shfl_sync(0xffffffffu, myidx, 16 + i);
            float4 a = __ldg(&P4[(long long)si * 64 + lane]);
            float4 b = __ldg(&P4[(long long)di * 64 + 32 + lane]);
            float4 h;
            h.x = fmaxf(a.x + b.x, 0.f);
            h.y = fmaxf(a.y + b.y, 0.f);
            h.z = fmaxf(a.z + b.z, 0.f);
            h.w = fmaxf(a.w + b.w, 0.f);
            uint2 uhi, ulo;
            split4(h, uhi, ulo);

            int row = w * 16 + i;
            int sub = lane >> 4;
            uint32_t boff = SWZ((uint32_t)(row * 128 + (lane & 15) * 8));
            char* pa = sm + sub * 16384 + boff;
            *(uint2*)(pa + A_HI_OFF) = uhi;
            *(uint2*)(pa + A_LO_OFF) = ulo;
        }
        __syncwarp();

        // ---- prefetch next tile's indices (hidden under MMA) ----
        int tn = t + grid;
        int nextidx = (tn < nTiles) ? load_idx(tn) : 0;

        // ---- fused 3-pass GEMM: Ahi·Bhi + Alo·Bhi + Ahi·Blo ----
        float acc[8][4];
#pragma unroll
        for (int nf = 0; nf < 8; nf++)
#pragma unroll
            for (int p = 0; p < 4; p++) acc[nf][p] = 0.f;

#pragma unroll
        for (int ks = 0; ks < 8; ks++) {
            uint32_t a_hi[4], a_lo[4];
            uint32_t aA = (aBaseHi + ((ks >> 2) * 16384)) ^ ((ks & 3) << 5);
            ldsm4(a_hi, aA);
            ldsm4(a_lo, aA + 32768);
#pragma unroll
            for (int nb = 0; nb < 4; nb++) {
                uint32_t bh[4], bl[4];
                uint32_t bA = bBase[ks] ^ (nb << 5);
                ldsm4t(bh, bA);
                ldsm4t(bl, bA + 16384);
                mma16816(acc[2 * nb],     a_hi, bh[0], bh[1]);
                mma16816(acc[2 * nb + 1], a_hi, bh[2], bh[3]);
                mma16816(acc[2 * nb],     a_lo, bh[0], bh[1]);
                mma16816(acc[2 * nb + 1], a_lo, bh[2], bh[3]);
                mma16816(acc[2 * nb],     a_hi, bl[0], bl[1]);
                mma16816(acc[2 * nb + 1], a_hi, bl[2], bl[3]);
            }
        }

        // ---- epilogue: +b2, relu, dot W3, 4-lane reduce, store ----
        float s1 = 0.f, s2 = 0.f;
#pragma unroll
        for (int nf = 0; nf < 8; nf++) {
            float4 bw = sBW4[nf * 4 + tq];
            s1 += fmaxf(acc[nf][0] + bw.x, 0.f) * bw.y
                + fmaxf(acc[nf][1] + bw.z, 0.f) * bw.w;
            s2 += fmaxf(acc[nf][2] + bw.x, 0.f) * bw.y
                + fmaxf(acc[nf][3] + bw.z, 0.f) * bw.w;
        }
        s1 += __shfl_xor_sync(0xffffffffu, s1, 1);
        s1 += __shfl_xor_sync(0xffffffffu, s1, 2);
        s2 += __shfl_xor_sync(0xffffffffu, s2, 1);
        s2 += __shfl_xor_sync(0xffffffffu, s2, 2);
        if (tq == 0) {
            int e1 = t * 128 + w * 16 + g;
            int e2 = e1 + 8;
            if (e1 < E) out[e1] = s1 + bias3;
            if (e2 < E) out[e2] = s2 + bias3;
        }
        myidx = nextidx;
        __syncwarp();   // fragment reads done before next tile's A stores
    }
}

// ---------------------------------------------------------------------------
extern "C" void kernel_launch(void* const* d_in, const int* in_sizes, int n_in,
                              void* d_out, int out_size) {
    const float* emb    = (const float*)d_in[0];
    const int*   eidx_w = (const int*)d_in[1];
    const float* W1     = (const float*)d_in[2];
    const float* b1     = (const float*)d_in[3];
    const float* W2     = (const float*)d_in[4];
    const float* b2     = (const float*)d_in[5];
    const float* W3     = (const float*)d_in[6];
    const float* b3     = (const float*)d_in[7];

    int N = in_sizes[0] / 128;
    int E = in_sizes[1] / 2;
    int nTilesP = (N + 127) / 128;
    int nTilesE = (E + 127) / 128;

    static int smem_set = 0;
    if (!smem_set) {
        cudaFuncSetAttribute(precompute_kernel,
                             cudaFuncAttributeMaxDynamicSharedMemorySize,
                             PRE_SMEM_BYTES);
        cudaFuncSetAttribute(edge_kernel,
                             cudaFuncAttributeMaxDynamicSharedMemorySize,
                             EDGE_SMEM_BYTES);
        smem_set = 1;
    }

    precompute_kernel<<<NSM, 256, PRE_SMEM_BYTES>>>(emb, W1, b1, N, nTilesP);
    edge_kernel<<<2 * NSM, 256, EDGE_SMEM_BYTES>>>(eidx_w, W2, b2, W3, b3,
                                                   (float*)d_out, E, N, nTilesE);
}